// round 16
// baseline (speedup 1.0000x reference)
#include <cuda_runtime.h>
#include <math.h>

#define B 512
#define MBD_B 64
#define MBD_C 16
#define FEAT 640

typedef unsigned long long u64;

__device__ __forceinline__ u64 pk2(float lo, float hi) {
    u64 r; asm("mov.b64 %0,{%1,%2};" : "=l"(r) : "f"(lo), "f"(hi)); return r;
}
__device__ __forceinline__ void upk2(float& lo, float& hi, u64 v) {
    asm("mov.b64 {%0,%1},%2;" : "=f"(lo), "=f"(hi) : "l"(v));
}
__device__ __forceinline__ u64 fma2(u64 a, u64 b, u64 c) {
    u64 d; asm("fma.rn.f32x2 %0,%1,%2,%3;" : "=l"(d) : "l"(a), "l"(b), "l"(c)); return d;
}
__device__ __forceinline__ u64 add2(u64 a, u64 b) {
    u64 d; asm("add.rn.f32x2 %0,%1,%2;" : "=l"(d) : "l"(a), "l"(b)); return d;
}

// ---------------- scratch (device globals; no allocation) ----------------
__device__ float g_h1[B * 20 * 12 * 12];      // conv1+pool output [img][ic20][12][12]
__device__ u64   g_w2d[20 * 40 * 5 * 5];      // conv2 weights pre-duplicated (w,w) [ic][oc][ky][kx]
__device__ float g_feats[B * FEAT];           // conv2+pool output, [img][oc*16+y*4+x]
__device__ float g_Mp[8][B * 1024];           // gemm k-split partials
__device__ float g_M[B * MBD_B * MBD_C];      // feats @ T^T, [i][1024]
__device__ float g_closep[4 * B * MBD_B];     // closeness partials [jc][i][64]

// ---------------- K0: repack conv2 weights -> duplicated u64 pairs ----------------
__global__ __launch_bounds__(256) void k_repack(const float* __restrict__ w) {
    int g = blockIdx.x * 256 + threadIdx.x;          // (ic,oc,ky) group
    if (g >= 20 * 40 * 5) return;
    int ic = g / 200, oc = (g / 5) % 40, ky = g % 5;
    const float* src = w + ((oc * 20 + ic) * 5 + ky) * 5;
    u64* dst = g_w2d + ((ic * 40 + oc) * 5 + ky) * 5;
    #pragma unroll
    for (int kx = 0; kx < 5; kx++) { float v = src[kx]; dst[kx] = pk2(v, v); }
}

// ---------------- K1: conv1 (1->20, 5x5) + relu + maxpool2 ----------------
__global__ __launch_bounds__(256) void k_conv1(const float* __restrict__ x,
                                               const float* __restrict__ w,
                                               const float* __restrict__ bias) {
    __shared__ float img[784];
    __shared__ float ws[500];
    __shared__ float bs[20];
    int b = blockIdx.x, tid = threadIdx.x;
    const float* xb = x + b * 784;
    for (int i = tid; i < 784; i += 256) img[i] = xb[i];
    for (int i = tid; i < 500; i += 256) ws[i] = w[i];
    if (tid < 20) bs[tid] = bias[tid];
    __syncthreads();
    if (tid >= 240) return;
    int oc = tid / 12, py = tid % 12;
    float acc[2][24];
    float bv = bs[oc];
    #pragma unroll
    for (int cy = 0; cy < 2; cy++)
        #pragma unroll
        for (int ox = 0; ox < 24; ox++) acc[cy][ox] = bv;
    #pragma unroll 1
    for (int ky = 0; ky < 5; ky++) {
        float wk[5];
        #pragma unroll
        for (int kx = 0; kx < 5; kx++) wk[kx] = ws[(oc * 5 + ky) * 5 + kx];
        #pragma unroll
        for (int cy = 0; cy < 2; cy++) {
            const float* r = img + (2 * py + cy + ky) * 28;
            float rr[28];
            #pragma unroll
            for (int i = 0; i < 28; i++) rr[i] = r[i];
            #pragma unroll
            for (int kx = 0; kx < 5; kx++)
                #pragma unroll
                for (int ox = 0; ox < 24; ox++)
                    acc[cy][ox] += rr[ox + kx] * wk[kx];
        }
    }
    float* out = g_h1 + (b * 20 + oc) * 144 + py * 12;
    #pragma unroll
    for (int px = 0; px < 12; px++) {
        float v = fmaxf(fmaxf(acc[0][2 * px], acc[0][2 * px + 1]),
                        fmaxf(acc[1][2 * px], acc[1][2 * px + 1]));
        out[px] = fmaxf(v, 0.f);
    }
}

// ---------------- K2: conv2, f32x2 with ZERO in-loop packing ----------------
// 320 thr = 40 oc x 4 py x 2 cy. Even pairs load straight from in2; odd pairs
// from a 1-float-shifted shadow (in2s); weights pre-duplicated u64 in smem.
__global__ __launch_bounds__(320) void k_conv2(const float* __restrict__ bias) {
    __shared__ float in2[2880];    // 20 ic x 144
    __shared__ float in2s[2880];   // in2s[i] = in2[i+1]
    __shared__ u64 wsd[1000];      // one ic: 40 oc x 5 ky x 5 kx duplicated
    int img = blockIdx.x, tid = threadIdx.x;
    const float4* src4 = (const float4*)(g_h1 + img * 2880);
    float4* in24 = (float4*)in2;
    for (int t = tid; t < 720; t += 320) in24[t] = src4[t];
    __syncthreads();
    for (int i = tid; i < 2879; i += 320) in2s[i] = in2[i + 1];
    if (tid == 0) in2s[2879] = 0.f;

    int oc = tid / 8, py = (tid % 8) / 2, cy = tid & 1;
    int rbase0 = (2 * py + cy) * 12;
    u64 acc[4] = {0ull, 0ull, 0ull, 0ull};

    #pragma unroll 1
    for (int ic = 0; ic < 20; ic++) {
        __syncthreads();
        const ulonglong2* wsrc = (const ulonglong2*)(g_w2d + ic * 1000);
        ulonglong2* wd2 = (ulonglong2*)wsd;
        for (int t = tid; t < 500; t += 320) wd2[t] = wsrc[t];
        __syncthreads();
        const u64* wb = wsd + oc * 25;
        int base = ic * 144 + rbase0;
        #pragma unroll
        for (int ky = 0; ky < 5; ky++) {
            const u64* wr = wb + ky * 5;
            u64 w0 = wr[0], w1 = wr[1], w2 = wr[2], w3 = wr[3], w4 = wr[4];
            const u64* pev = (const u64*)(in2 + base + ky * 12);
            const u64* pov = (const u64*)(in2s + base + ky * 12);
            u64 pe0 = pev[0], pe1 = pev[1], pe2 = pev[2],
                pe3 = pev[3], pe4 = pev[4], pe5 = pev[5];
            u64 po0 = pov[0], po1 = pov[1], po2 = pov[2],
                po3 = pov[3], po4 = pov[4];
            acc[0] = fma2(pe0, w0, acc[0]);
            acc[0] = fma2(po0, w1, acc[0]);
            acc[0] = fma2(pe1, w2, acc[0]);
            acc[0] = fma2(po1, w3, acc[0]);
            acc[0] = fma2(pe2, w4, acc[0]);
            acc[1] = fma2(pe1, w0, acc[1]);
            acc[1] = fma2(po1, w1, acc[1]);
            acc[1] = fma2(pe2, w2, acc[1]);
            acc[1] = fma2(po2, w3, acc[1]);
            acc[1] = fma2(pe3, w4, acc[1]);
            acc[2] = fma2(pe2, w0, acc[2]);
            acc[2] = fma2(po2, w1, acc[2]);
            acc[2] = fma2(pe3, w2, acc[2]);
            acc[2] = fma2(po3, w3, acc[2]);
            acc[2] = fma2(pe4, w4, acc[2]);
            acc[3] = fma2(pe3, w0, acc[3]);
            acc[3] = fma2(po3, w1, acc[3]);
            acc[3] = fma2(pe4, w2, acc[3]);
            acc[3] = fma2(po4, w3, acc[3]);
            acc[3] = fma2(pe5, w4, acc[3]);
        }
    }
    float bv = bias[oc];
    #pragma unroll
    for (int p = 0; p < 4; p++) {
        float lo, hi;
        upk2(lo, hi, acc[p]);
        float m = fmaxf(lo, hi);
        float other = __shfl_xor_sync(0xffffffffu, m, 1);
        if (cy == 0) {
            float v = fmaxf(m, other) + bv;
            g_feats[img * 640 + oc * 16 + py * 4 + p] = fmaxf(v, 0.f);
        }
    }
}

// ---------------- K3: M = feats @ T^T, scalar fp32, K-split 8 ----------------
#define GBM 64
#define GBN 64
#define GBK 16
#define KSPLIT 8
#define KCH (FEAT / KSPLIT)   // 80
__global__ __launch_bounds__(256) void k_gemm(const float* __restrict__ Tm) {
    __shared__ float As[GBK][GBM];   // 4KB
    __shared__ float Bs[GBK][GBN];   // 4KB
    int bn = blockIdx.x, bm = blockIdx.y, bz = blockIdx.z;
    int tid = threadIdx.x;
    int ty = tid / 16, tx = tid % 16;
    float acc[4][4] = {};
    const float* A = g_feats + (bm * GBM) * FEAT;
    const float* Bmat = Tm + (bn * GBN) * FEAT;
    int m_st = tid / 4, kq = tid % 4;
    for (int k0 = bz * KCH; k0 < (bz + 1) * KCH; k0 += GBK) {
        float4 va = *(const float4*)(A + m_st * FEAT + k0 + kq * 4);
        float4 vb = *(const float4*)(Bmat + m_st * FEAT + k0 + kq * 4);
        __syncthreads();
        As[kq * 4 + 0][m_st] = va.x; As[kq * 4 + 1][m_st] = va.y;
        As[kq * 4 + 2][m_st] = va.z; As[kq * 4 + 3][m_st] = va.w;
        Bs[kq * 4 + 0][m_st] = vb.x; Bs[kq * 4 + 1][m_st] = vb.y;
        Bs[kq * 4 + 2][m_st] = vb.z; Bs[kq * 4 + 3][m_st] = vb.w;
        __syncthreads();
        #pragma unroll
        for (int kk = 0; kk < GBK; kk++) {
            float4 a4 = *(const float4*)(&As[kk][ty * 4]);
            float4 b4 = *(const float4*)(&Bs[kk][tx * 4]);
            float a[4] = {a4.x, a4.y, a4.z, a4.w};
            float bb[4] = {b4.x, b4.y, b4.z, b4.w};
            #pragma unroll
            for (int i = 0; i < 4; i++)
                #pragma unroll
                for (int j = 0; j < 4; j++) acc[i][j] += a[i] * bb[j];
        }
    }
    float* outp = g_Mp[bz];
    #pragma unroll
    for (int i = 0; i < 4; i++) {
        int r = bm * GBM + ty * 4 + i;
        *(float4*)(outp + r * 1024 + bn * GBN + tx * 4) =
            make_float4(acc[i][0], acc[i][1], acc[i][2], acc[i][3]);
    }
}

// ---------------- K3b: combine k-split partials (fixed order -> deterministic) ----
__global__ __launch_bounds__(256) void k_comb() {
    int t = blockIdx.x * 256 + threadIdx.x;
    const float4* p0 = (const float4*)g_Mp[0];
    const float4* p1 = (const float4*)g_Mp[1];
    const float4* p2 = (const float4*)g_Mp[2];
    const float4* p3 = (const float4*)g_Mp[3];
    const float4* p4 = (const float4*)g_Mp[4];
    const float4* p5 = (const float4*)g_Mp[5];
    const float4* p6 = (const float4*)g_Mp[6];
    const float4* p7 = (const float4*)g_Mp[7];
    float4 a = p0[t], b = p1[t], c = p2[t], d = p3[t];
    float4 e = p4[t], f = p5[t], g = p6[t], h = p7[t];
    float4 r;
    r.x = ((a.x + b.x) + (c.x + d.x)) + ((e.x + f.x) + (g.x + h.x));
    r.y = ((a.y + b.y) + (c.y + d.y)) + ((e.y + f.y) + (g.y + h.y));
    r.z = ((a.z + b.z) + (c.z + d.z)) + ((e.z + f.z) + (g.z + h.z));
    r.w = ((a.w + b.w) + (c.w + d.w)) + ((e.w + f.w) + (g.w + h.w));
    ((float4*)g_M)[t] = r;
}

// ---------------- K4: mbd closeness, f32x2 + packed abs, 2 i-rows per thread ------
__global__ __launch_bounds__(128) void k_mbd() {
    __shared__ u64 s2[128][8];
    int bcol = blockIdx.x, jc = blockIdx.y, it = blockIdx.z;
    int tid = threadIdx.x;
    int jbase = jc * 128;
    const float4* Ms = (const float4*)g_M;
    for (int t = tid; t < 512; t += 128) {
        int j = t >> 2, q = t & 3;
        float4 v = Ms[((jbase + j) * 1024 + bcol * 16) / 4 + q];
        s2[j][2 * q] = pk2(-v.x, -v.y);
        s2[j][2 * q + 1] = pk2(-v.z, -v.w);
    }
    int i0 = it * 256 + tid;
    int i1 = i0 + 128;
    u64 m0[8], m1[8];
    {
        const float4* mi0 = (const float4*)(g_M + i0 * 1024 + bcol * 16);
        const float4* mi1 = (const float4*)(g_M + i1 * 1024 + bcol * 16);
        #pragma unroll
        for (int q = 0; q < 4; q++) {
            float4 v = mi0[q];
            m0[2 * q] = pk2(v.x, v.y); m0[2 * q + 1] = pk2(v.z, v.w);
            float4 u = mi1[q];
            m1[2 * q] = pk2(u.x, u.y); m1[2 * q + 1] = pk2(u.z, u.w);
        }
    }
    __syncthreads();
    const u64 MASK = 0x7FFFFFFF7FFFFFFFull;
    float acc0 = 0.f, acc1 = 0.f;
    #pragma unroll 2
    for (int j = 0; j < 128; j++) {
        u64 sj[8];
        #pragma unroll
        for (int q = 0; q < 8; q++) sj[q] = s2[j][q];
        u64 t0[8], t1[8];
        #pragma unroll
        for (int q = 0; q < 8; q++) t0[q] = add2(m0[q], sj[q]) & MASK;
        #pragma unroll
        for (int q = 0; q < 8; q++) t1[q] = add2(m1[q], sj[q]) & MASK;
        u64 a01 = add2(t0[0], t0[1]), a23 = add2(t0[2], t0[3]);
        u64 a45 = add2(t0[4], t0[5]), a67 = add2(t0[6], t0[7]);
        u64 b01 = add2(t1[0], t1[1]), b23 = add2(t1[2], t1[3]);
        u64 b45 = add2(t1[4], t1[5]), b67 = add2(t1[6], t1[7]);
        u64 aa = add2(add2(a01, a23), add2(a45, a67));
        u64 bb = add2(add2(b01, b23), add2(b45, b67));
        float lo0, hi0, lo1, hi1;
        upk2(lo0, hi0, aa);
        upk2(lo1, hi1, bb);
        acc0 += __expf(-(lo0 + hi0));
        acc1 += __expf(-(lo1 + hi1));
    }
    g_closep[(jc * B + i0) * 64 + bcol] = acc0;
    g_closep[(jc * B + i1) * 64 + bcol] = acc1;
}

// ---------------- K5: concat + fc1 + relu + fc2 + sigmoid, 2 rows/block -----------
__global__ __launch_bounds__(256) void k_fc(const float* __restrict__ w1,
                                            const float* __restrict__ b1,
                                            const float* __restrict__ w2,
                                            const float* __restrict__ b2,
                                            float* __restrict__ out) {
    __shared__ float sin_[2][704];
    __shared__ float h[2][100];
    int row0 = blockIdx.x * 2;
    int tid = threadIdx.x;
    for (int t = tid; t < 2 * 704; t += 256) {
        int r = t / 704, c = t % 704;
        if (c < 640) {
            sin_[r][c] = g_feats[(row0 + r) * 640 + c];
        } else {
            int bcol = c - 640, i = row0 + r;
            float v = 0.f;
            #pragma unroll
            for (int jc = 0; jc < 4; jc++) v += g_closep[(jc * B + i) * 64 + bcol];
            sin_[r][c] = v;
        }
    }
    __syncthreads();
    for (int o = tid; o < 200; o += 256) {
        int r = o / 100, c = o % 100;
        const float4* wrow = (const float4*)(w1 + c * 704);
        const float4* xin = (const float4*)(&sin_[r][0]);
        float acc = 0.f;
        #pragma unroll 4
        for (int k = 0; k < 176; k++) {
            float4 wv = wrow[k], xv = xin[k];
            acc += wv.x * xv.x + wv.y * xv.y + wv.z * xv.z + wv.w * xv.w;
        }
        h[r][c] = fmaxf(acc + b1[c], 0.f);
    }
    __syncthreads();
    int w = tid / 32, lane = tid % 32;
    if (w < 2) {
        float a = 0.f;
        for (int c = lane; c < 100; c += 32) a += h[w][c] * w2[c];
        #pragma unroll
        for (int off = 16; off; off >>= 1) a += __shfl_down_sync(0xffffffffu, a, off);
        if (lane == 0) {
            float z = a + b2[0];
            out[row0 + w] = 1.f / (1.f + __expf(-z));
        }
    }
}

// ---------------- launch ----------------
extern "C" void kernel_launch(void* const* d_in, const int* in_sizes, int n_in,
                              void* d_out, int out_size) {
    const float* x       = (const float*)d_in[0];
    const float* conv1_w = (const float*)d_in[1];
    const float* conv1_b = (const float*)d_in[2];
    const float* conv2_w = (const float*)d_in[3];
    const float* conv2_b = (const float*)d_in[4];
    const float* Tm      = (const float*)d_in[5];
    const float* fc1_w   = (const float*)d_in[6];
    const float* fc1_b   = (const float*)d_in[7];
    const float* fc2_w   = (const float*)d_in[8];
    const float* fc2_b   = (const float*)d_in[9];
    float* out = (float*)d_out;

    k_repack<<<16, 256>>>(conv2_w);
    k_conv1<<<B, 256>>>(x, conv1_w, conv1_b);
    k_conv2<<<B, 320>>>(conv2_b);
    dim3 g3(1024 / GBN, B / GBM, KSPLIT);
    k_gemm<<<g3, 256>>>(Tm);
    k_comb<<<512, 256>>>();
    dim3 g4(64, 4, 2);
    k_mbd<<<g4, 128>>>();
    k_fc<<<256, 256>>>(fc1_w, fc1_b, fc2_w, fc2_b, out);
}

// round 17
// speedup vs baseline: 1.1370x; 1.1370x over previous
#include <cuda_runtime.h>
#include <math.h>

#define B 512
#define MBD_B 64
#define MBD_C 16
#define FEAT 640

typedef unsigned long long u64;

__device__ __forceinline__ u64 pk2(float lo, float hi) {
    u64 r; asm("mov.b64 %0,{%1,%2};" : "=l"(r) : "f"(lo), "f"(hi)); return r;
}
__device__ __forceinline__ void upk2(float& lo, float& hi, u64 v) {
    asm("mov.b64 {%0,%1},%2;" : "=f"(lo), "=f"(hi) : "l"(v));
}
__device__ __forceinline__ u64 fma2(u64 a, u64 b, u64 c) {
    u64 d; asm("fma.rn.f32x2 %0,%1,%2,%3;" : "=l"(d) : "l"(a), "l"(b), "l"(c)); return d;
}
__device__ __forceinline__ u64 add2(u64 a, u64 b) {
    u64 d; asm("add.rn.f32x2 %0,%1,%2;" : "=l"(d) : "l"(a), "l"(b)); return d;
}

// ---------------- scratch (device globals; no allocation) ----------------
__device__ float g_h1[B * 20 * 12 * 12];      // conv1+pool output [img][ic20][12][12]
__device__ float g_w2[20 * 40 * 5 * 8];       // repacked conv2 weights [ic][oc][ky][kx pad8]
__device__ float g_feats[B * FEAT];           // conv2+pool output, [img][oc*16+y*4+x]
__device__ float g_Mp[8][B * 1024];           // gemm k-split partials
__device__ float g_M[B * MBD_B * MBD_C];      // feats @ T^T, [i][1024]
__device__ float g_closep[8 * B * MBD_B];     // closeness partials [jc][i][64]

// ---------------- K0: repack conv2 weights: w[oc][ic][ky][kx5] -> g_w2[ic][oc][ky][kx8]
__global__ __launch_bounds__(256) void k_repack(const float* __restrict__ w) {
    int g = blockIdx.x * 256 + threadIdx.x;          // (ic,oc,ky) group
    if (g >= 20 * 40 * 5) return;
    int ic = g / 200, oc = (g / 5) % 40, ky = g % 5;
    const float* src = w + ((oc * 20 + ic) * 5 + ky) * 5;
    float* dst = g_w2 + ((ic * 40 + oc) * 5 + ky) * 8;
    #pragma unroll
    for (int kx = 0; kx < 8; kx++) dst[kx] = (kx < 5) ? src[kx] : 0.f;
}

// ---------------- K1: conv1 (1->20, 5x5) + relu + maxpool2 ----------------
__global__ __launch_bounds__(256) void k_conv1(const float* __restrict__ x,
                                               const float* __restrict__ w,
                                               const float* __restrict__ bias) {
    __shared__ float img[784];
    __shared__ float ws[500];
    __shared__ float bs[20];
    int b = blockIdx.x, tid = threadIdx.x;
    const float* xb = x + b * 784;
    for (int i = tid; i < 784; i += 256) img[i] = xb[i];
    for (int i = tid; i < 500; i += 256) ws[i] = w[i];
    if (tid < 20) bs[tid] = bias[tid];
    __syncthreads();
    if (tid >= 240) return;
    int oc = tid / 12, py = tid % 12;
    float acc[2][24];
    float bv = bs[oc];
    #pragma unroll
    for (int cy = 0; cy < 2; cy++)
        #pragma unroll
        for (int ox = 0; ox < 24; ox++) acc[cy][ox] = bv;
    #pragma unroll 1
    for (int ky = 0; ky < 5; ky++) {
        float wk[5];
        #pragma unroll
        for (int kx = 0; kx < 5; kx++) wk[kx] = ws[(oc * 5 + ky) * 5 + kx];
        #pragma unroll
        for (int cy = 0; cy < 2; cy++) {
            const float* r = img + (2 * py + cy + ky) * 28;
            float rr[28];
            #pragma unroll
            for (int i = 0; i < 28; i++) rr[i] = r[i];
            #pragma unroll
            for (int kx = 0; kx < 5; kx++)
                #pragma unroll
                for (int ox = 0; ox < 24; ox++)
                    acc[cy][ox] += rr[ox + kx] * wk[kx];
        }
    }
    float* out = g_h1 + (b * 20 + oc) * 144 + py * 12;
    #pragma unroll
    for (int px = 0; px < 12; px++) {
        float v = fmaxf(fmaxf(acc[0][2 * px], acc[0][2 * px + 1]),
                        fmaxf(acc[1][2 * px], acc[1][2 * px + 1]));
        out[px] = fmaxf(v, 0.f);
    }
}

// ---------------- K2: conv2 (20->40, 5x5) + relu + maxpool2, f32x2, fused -------
__global__ __launch_bounds__(320) void k_conv2(const float* __restrict__ bias) {
    __shared__ float in2[2880];   // 20 ic x 144
    __shared__ float ws[1600];    // one ic: 40 oc x 5 ky x 8 (kx padded)
    int img = blockIdx.x, tid = threadIdx.x;
    const float4* src4 = (const float4*)(g_h1 + img * 2880);
    float4* in24 = (float4*)in2;
    for (int t = tid; t < 720; t += 320) in24[t] = src4[t];

    int oc = tid / 8, py = (tid % 8) / 2, cy = tid & 1;
    u64 acc[4] = {0ull, 0ull, 0ull, 0ull};

    #pragma unroll 1
    for (int ic = 0; ic < 20; ic++) {
        __syncthreads();
        const float4* wsrc = (const float4*)(g_w2 + ic * 1600);
        float4* ws4 = (float4*)ws;
        for (int t = tid; t < 400; t += 320) ws4[t] = wsrc[t];
        __syncthreads();
        const float* wb = ws + oc * 40;
        const float* inb = in2 + ic * 144 + (2 * py + cy) * 12;
        #pragma unroll
        for (int ky = 0; ky < 5; ky++) {
            const float* wr = wb + ky * 8;
            float wk0 = wr[0], wk1 = wr[1], wk2 = wr[2], wk3 = wr[3], wk4 = wr[4];
            u64 wp0 = pk2(wk0, wk0), wp1 = pk2(wk1, wk1), wp2 = pk2(wk2, wk2);
            u64 wp3 = pk2(wk3, wk3), wp4 = pk2(wk4, wk4);
            const float4* r4 = (const float4*)(inb + ky * 12);
            float4 q0 = r4[0], q1 = r4[1], q2 = r4[2];
            float rr[12] = {q0.x, q0.y, q0.z, q0.w, q1.x, q1.y, q1.z, q1.w,
                            q2.x, q2.y, q2.z, q2.w};
            u64 pe[6], po[5];
            #pragma unroll
            for (int t = 0; t < 6; t++) pe[t] = pk2(rr[2 * t], rr[2 * t + 1]);
            #pragma unroll
            for (int t = 0; t < 5; t++) po[t] = pk2(rr[2 * t + 1], rr[2 * t + 2]);
            #pragma unroll
            for (int p = 0; p < 4; p++) {
                acc[p] = fma2(pe[p], wp0, acc[p]);
                acc[p] = fma2(po[p], wp1, acc[p]);
                acc[p] = fma2(pe[p + 1], wp2, acc[p]);
                acc[p] = fma2(po[p + 1], wp3, acc[p]);
                acc[p] = fma2(pe[p + 2], wp4, acc[p]);
            }
        }
    }
    float bv = bias[oc];
    #pragma unroll
    for (int p = 0; p < 4; p++) {
        float lo, hi;
        upk2(lo, hi, acc[p]);
        float m = fmaxf(lo, hi);
        float other = __shfl_xor_sync(0xffffffffu, m, 1);
        if (cy == 0) {
            float v = fmaxf(m, other) + bv;
            g_feats[img * 640 + oc * 16 + py * 4 + p] = fmaxf(v, 0.f);
        }
    }
}

// ---------------- K3: M = feats @ T^T, scalar fp32, K-split 8 ----------------
#define GBM 64
#define GBN 64
#define GBK 16
#define KSPLIT 8
#define KCH (FEAT / KSPLIT)   // 80
__global__ __launch_bounds__(256) void k_gemm(const float* __restrict__ Tm) {
    __shared__ float As[GBK][GBM];   // 4KB
    __shared__ float Bs[GBK][GBN];   // 4KB
    int bn = blockIdx.x, bm = blockIdx.y, bz = blockIdx.z;
    int tid = threadIdx.x;
    int ty = tid / 16, tx = tid % 16;
    float acc[4][4] = {};
    const float* A = g_feats + (bm * GBM) * FEAT;
    const float* Bmat = Tm + (bn * GBN) * FEAT;
    int m_st = tid / 4, kq = tid % 4;
    for (int k0 = bz * KCH; k0 < (bz + 1) * KCH; k0 += GBK) {
        float4 va = *(const float4*)(A + m_st * FEAT + k0 + kq * 4);
        float4 vb = *(const float4*)(Bmat + m_st * FEAT + k0 + kq * 4);
        __syncthreads();
        As[kq * 4 + 0][m_st] = va.x; As[kq * 4 + 1][m_st] = va.y;
        As[kq * 4 + 2][m_st] = va.z; As[kq * 4 + 3][m_st] = va.w;
        Bs[kq * 4 + 0][m_st] = vb.x; Bs[kq * 4 + 1][m_st] = vb.y;
        Bs[kq * 4 + 2][m_st] = vb.z; Bs[kq * 4 + 3][m_st] = vb.w;
        __syncthreads();
        #pragma unroll
        for (int kk = 0; kk < GBK; kk++) {
            float4 a4 = *(const float4*)(&As[kk][ty * 4]);
            float4 b4 = *(const float4*)(&Bs[kk][tx * 4]);
            float a[4] = {a4.x, a4.y, a4.z, a4.w};
            float bb[4] = {b4.x, b4.y, b4.z, b4.w};
            #pragma unroll
            for (int i = 0; i < 4; i++)
                #pragma unroll
                for (int j = 0; j < 4; j++) acc[i][j] += a[i] * bb[j];
        }
    }
    float* outp = g_Mp[bz];
    #pragma unroll
    for (int i = 0; i < 4; i++) {
        int r = bm * GBM + ty * 4 + i;
        *(float4*)(outp + r * 1024 + bn * GBN + tx * 4) =
            make_float4(acc[i][0], acc[i][1], acc[i][2], acc[i][3]);
    }
}

// ---------------- K3b: combine k-split partials (fixed order -> deterministic) ----
__global__ __launch_bounds__(256) void k_comb() {
    int t = blockIdx.x * 256 + threadIdx.x;
    const float4* p0 = (const float4*)g_Mp[0];
    const float4* p1 = (const float4*)g_Mp[1];
    const float4* p2 = (const float4*)g_Mp[2];
    const float4* p3 = (const float4*)g_Mp[3];
    const float4* p4 = (const float4*)g_Mp[4];
    const float4* p5 = (const float4*)g_Mp[5];
    const float4* p6 = (const float4*)g_Mp[6];
    const float4* p7 = (const float4*)g_Mp[7];
    float4 a = p0[t], b = p1[t], c = p2[t], d = p3[t];
    float4 e = p4[t], f = p5[t], g = p6[t], h = p7[t];
    float4 r;
    r.x = ((a.x + b.x) + (c.x + d.x)) + ((e.x + f.x) + (g.x + h.x));
    r.y = ((a.y + b.y) + (c.y + d.y)) + ((e.y + f.y) + (g.y + h.y));
    r.z = ((a.z + b.z) + (c.z + d.z)) + ((e.z + f.z) + (g.z + h.z));
    r.w = ((a.w + b.w) + (c.w + d.w)) + ((e.w + f.w) + (g.w + h.w));
    ((float4*)g_M)[t] = r;
}

// ---------------- K4: mbd closeness, f32x2 + packed abs, j-split 8 ----------------
// grid (64 bcol, 8 jchunk, 2 itile), 128 threads; 64 j-rows staged (4KB),
// 2 independent i-chains per thread.
__global__ __launch_bounds__(128) void k_mbd() {
    __shared__ u64 s2[64][8];     // negated M[jbase+j][bcol*16..+15], c-pairs
    int bcol = blockIdx.x, jc = blockIdx.y, it = blockIdx.z;
    int tid = threadIdx.x;
    int jbase = jc * 64;
    const float4* Ms = (const float4*)g_M;
    for (int t = tid; t < 256; t += 128) {
        int j = t >> 2, q = t & 3;
        float4 v = Ms[((jbase + j) * 1024 + bcol * 16) / 4 + q];
        s2[j][2 * q] = pk2(-v.x, -v.y);
        s2[j][2 * q + 1] = pk2(-v.z, -v.w);
    }
    int i0 = it * 256 + tid;
    int i1 = i0 + 128;
    u64 m0[8], m1[8];
    {
        const float4* mi0 = (const float4*)(g_M + i0 * 1024 + bcol * 16);
        const float4* mi1 = (const float4*)(g_M + i1 * 1024 + bcol * 16);
        #pragma unroll
        for (int q = 0; q < 4; q++) {
            float4 v = mi0[q];
            m0[2 * q] = pk2(v.x, v.y); m0[2 * q + 1] = pk2(v.z, v.w);
            float4 u = mi1[q];
            m1[2 * q] = pk2(u.x, u.y); m1[2 * q + 1] = pk2(u.z, u.w);
        }
    }
    __syncthreads();
    const u64 MASK = 0x7FFFFFFF7FFFFFFFull;
    float acc0 = 0.f, acc1 = 0.f;
    #pragma unroll 2
    for (int j = 0; j < 64; j++) {
        u64 sj[8];
        #pragma unroll
        for (int q = 0; q < 8; q++) sj[q] = s2[j][q];
        u64 t0[8], t1[8];
        #pragma unroll
        for (int q = 0; q < 8; q++) t0[q] = add2(m0[q], sj[q]) & MASK;
        #pragma unroll
        for (int q = 0; q < 8; q++) t1[q] = add2(m1[q], sj[q]) & MASK;
        u64 a01 = add2(t0[0], t0[1]), a23 = add2(t0[2], t0[3]);
        u64 a45 = add2(t0[4], t0[5]), a67 = add2(t0[6], t0[7]);
        u64 b01 = add2(t1[0], t1[1]), b23 = add2(t1[2], t1[3]);
        u64 b45 = add2(t1[4], t1[5]), b67 = add2(t1[6], t1[7]);
        u64 aa = add2(add2(a01, a23), add2(a45, a67));
        u64 bb = add2(add2(b01, b23), add2(b45, b67));
        float lo0, hi0, lo1, hi1;
        upk2(lo0, hi0, aa);
        upk2(lo1, hi1, bb);
        acc0 += __expf(-(lo0 + hi0));
        acc1 += __expf(-(lo1 + hi1));
    }
    g_closep[(jc * B + i0) * 64 + bcol] = acc0;
    g_closep[(jc * B + i1) * 64 + bcol] = acc1;
}

// ---------------- K5: concat (sum 8 partials, fixed order) + fc1 + relu + fc2 ----
__global__ __launch_bounds__(256) void k_fc(const float* __restrict__ w1,
                                            const float* __restrict__ b1,
                                            const float* __restrict__ w2,
                                            const float* __restrict__ b2,
                                            float* __restrict__ out) {
    __shared__ float sin_[4][704];
    __shared__ float h[4][100];
    int row0 = blockIdx.x * 4;
    int tid = threadIdx.x;
    for (int t = tid; t < 4 * 704; t += 256) {
        int r = t / 704, c = t % 704;
        if (c < 640) {
            sin_[r][c] = g_feats[(row0 + r) * 640 + c];
        } else {
            int bcol = c - 640, i = row0 + r;
            float v = 0.f;
            #pragma unroll
            for (int jc = 0; jc < 8; jc++) v += g_closep[(jc * B + i) * 64 + bcol];
            sin_[r][c] = v;
        }
    }
    __syncthreads();
    for (int o = tid; o < 400; o += 256) {
        int r = o / 100, c = o % 100;
        const float4* wrow = (const float4*)(w1 + c * 704);
        const float4* xin = (const float4*)(&sin_[r][0]);
        float acc = 0.f;
        #pragma unroll 4
        for (int k = 0; k < 176; k++) {
            float4 wv = wrow[k], xv = xin[k];
            acc += wv.x * xv.x + wv.y * xv.y + wv.z * xv.z + wv.w * xv.w;
        }
        h[r][c] = fmaxf(acc + b1[c], 0.f);
    }
    __syncthreads();
    int w = tid / 32, lane = tid % 32;
    if (w < 4) {
        float a = 0.f;
        for (int c = lane; c < 100; c += 32) a += h[w][c] * w2[c];
        #pragma unroll
        for (int off = 16; off; off >>= 1) a += __shfl_down_sync(0xffffffffu, a, off);
        if (lane == 0) {
            float z = a + b2[0];
            out[row0 + w] = 1.f / (1.f + __expf(-z));
        }
    }
}

// ---------------- launch ----------------
extern "C" void kernel_launch(void* const* d_in, const int* in_sizes, int n_in,
                              void* d_out, int out_size) {
    const float* x       = (const float*)d_in[0];
    const float* conv1_w = (const float*)d_in[1];
    const float* conv1_b = (const float*)d_in[2];
    const float* conv2_w = (const float*)d_in[3];
    const float* conv2_b = (const float*)d_in[4];
    const float* Tm      = (const float*)d_in[5];
    const float* fc1_w   = (const float*)d_in[6];
    const float* fc1_b   = (const float*)d_in[7];
    const float* fc2_w   = (const float*)d_in[8];
    const float* fc2_b   = (const float*)d_in[9];
    float* out = (float*)d_out;

    k_repack<<<16, 256>>>(conv2_w);
    k_conv1<<<B, 256>>>(x, conv1_w, conv1_b);
    k_conv2<<<B, 320>>>(conv2_b);
    dim3 g3(1024 / GBN, B / GBM, KSPLIT);
    k_gemm<<<g3, 256>>>(Tm);
    k_comb<<<512, 256>>>();
    dim3 g4(64, 8, 2);
    k_mbd<<<g4, 128>>>();
    k_fc<<<128, 256>>>(fc1_w, fc1_b, fc2_w, fc2_b, out);
}